// round 15
// baseline (speedup 1.0000x reference)
#include <cuda_runtime.h>
#include <cuda_bf16.h>
#include <cuda_fp16.h>
#include <math.h>
#include <stdint.h>

// Problem constants
#define BATCH 2
#define SEQ 2048
#define DMODEL 1024
#define NHEADS 16
#define HDIM 64
#define MROWS (BATCH*SEQ)              // 4096
#define OUTN  (BATCH*SEQ*DMODEL)       // 4194304
#define KVN   (BATCH*NHEADS*SEQ*HDIM)  // 4194304
#define WN    (DMODEL*DMODEL)          // 1048576
#define ROPEN (SEQ*32)                 // 65536

// ---------------- scratch (device globals; no allocations allowed) ----------
__device__ float g_kfb[KVN];
__device__ float g_vfb[KVN];
__device__ __half g_xh[OUTN];          // activation fp16 (x, then attn-out)
__device__ __half g_wq[WN], g_wk[WN], g_wv[WN], g_wo[WN];   // weights fp16
__device__ __half g_qhf[KVN];          // Q fp16 (pre-scaled by 0.125*log2e)
__device__ __half g_khf[KVN];          // K fp16
__device__ __half g_vhf[KVN];          // V fp16
__device__ float2 g_rope[ROPEN];       // (cos, sin) LUT [s][p]

// ====================== helpers ==============================================
__device__ __forceinline__ uint32_t smem_to_u32(const void* p) {
    uint32_t a;
    asm("{ .reg .u64 t; cvta.to.shared.u64 t, %1; cvt.u32.u64 %0, t; }"
        : "=r"(a) : "l"(p));
    return a;
}

__device__ __forceinline__ void cp16(uint32_t saddr, const void* g) {
    asm volatile("cp.async.cg.shared.global [%0], [%1], 16;"
                 :: "r"(saddr), "l"(g) : "memory");
}

__device__ __forceinline__ float ex2f(float x) {
    float y;
    asm("ex2.approx.ftz.f32 %0, %1;" : "=f"(y) : "f"(x));
    return y;
}

#define LDSM4(r0, r1, r2, r3, addr) \
    asm volatile("ldmatrix.sync.aligned.m8n8.x4.shared.b16 {%0,%1,%2,%3}, [%4];" \
                 : "=r"(r0), "=r"(r1), "=r"(r2), "=r"(r3) : "r"(addr))

#define LDSM4T(r0, r1, r2, r3, addr) \
    asm volatile("ldmatrix.sync.aligned.m8n8.x4.trans.shared.b16 {%0,%1,%2,%3}, [%4];" \
                 : "=r"(r0), "=r"(r1), "=r"(r2), "=r"(r3) : "r"(addr))

#define MMA16816F16(d, a0, a1, a2, a3, b0, b1) \
    asm volatile("mma.sync.aligned.m16n8k16.row.col.f32.f16.f16.f32 " \
                 "{%0,%1,%2,%3}, {%4,%5,%6,%7}, {%8,%9}, {%0,%1,%2,%3};" \
                 : "+f"((d)[0]), "+f"((d)[1]), "+f"((d)[2]), "+f"((d)[3]) \
                 : "r"(a0), "r"(a1), "r"(a2), "r"(a3), "r"(b0), "r"(b1))

struct RopeTab { float hi[32]; float lo[32]; };

// ====================== merged conversions + rope LUT =========================
struct ConvPtrs {
    const float4* x;
    __half2* xh;
    const float4* w[4];
    __half2* wd[4];
    float2* rope;
};

__global__ void conv_all(ConvPtrs p, RopeTab tab, int nx4, int nw4)
{
    int i = blockIdx.x * blockDim.x + threadIdx.x;
    int sl = blockIdx.y;
    if (sl == 0) {
        if (i >= nx4) return;
        float4 v = p.x[i];
        p.xh[2*i]   = __floats2half2_rn(v.x, v.y);
        p.xh[2*i+1] = __floats2half2_rn(v.z, v.w);
    } else if (sl <= 4) {
        if (i >= nw4) return;
        int w = sl - 1;
        float4 v = p.w[w][i];
        p.wd[w][2*i]   = __floats2half2_rn(v.x, v.y);
        p.wd[w][2*i+1] = __floats2half2_rn(v.z, v.w);
    } else {
        if (i >= ROPEN) return;
        int s = i >> 5, pp = i & 31;
        float fs = (float)s;
        float ang = fmaf(fs, tab.lo[pp], fs * tab.hi[pp]);
        float c, sn;
        sincosf(ang, &sn, &c);
        p.rope[i] = make_float2(c, sn);
    }
}

// ====================== GEMM cores (3-stage ring, 1 sync/chunk) ===============
#define NCK 16
#define NSTAGE 3

// ---- wide core: 128x128 CTA tile (ogemm). Stage: A 16K + B 16K = 32KB -------
#define WTBA 16384
#define WSTAGE 32768
#define WGEMM_SMEM (NSTAGE*WSTAGE)   // 98304

__device__ __forceinline__ void stage_load_w(uint32_t sb,
    const uint4* __restrict__ A4, const uint4* __restrict__ B4,
    int m0, int n0, int c, int tid)
{
    const int q = tid & 7;
    const int r0 = tid >> 3;
#pragma unroll
    for (int it = 0; it < 4; it++) {
        int row = r0 + it * 32;
        uint32_t off = row * 128 + q * 16;
        off ^= (off >> 3) & 0x70;
        cp16(sb + off,        A4 + (size_t)(m0 + row) * 128 + c * 8 + q);
        cp16(sb + WTBA + off, B4 + (size_t)(n0 + row) * 128 + c * 8 + q);
    }
}

__global__ void __launch_bounds__(256, 2) mma_gemm(const __half* __restrict__ A_,
                                                   const __half* __restrict__ B_,
                                                   float* __restrict__ C)
{
    extern __shared__ char smem[];
    const uint32_t sbase = smem_to_u32(smem);
    const int tid = threadIdx.x;
    const int wid = tid >> 5;
    const int lane = tid & 31;
    const int m0 = blockIdx.y * 128;
    const int n0 = blockIdx.x * 128;
    const int wm = (wid & 1) * 64;
    const int wn = (wid >> 1) * 32;
    const int t  = lane >> 3;
    const int li = lane & 7;
    const int arow  = (t & 1) * 8 + li;
    const int acolb = (t >> 1) * 16;
    const int brow  = ((t >> 1) & 1) * 8 + li;
    const int bcolb = (t & 1) * 16;

    const uint4* A4 = (const uint4*)A_;
    const uint4* B4 = (const uint4*)B_;

    float acc[4][4][4];
#pragma unroll
    for (int i = 0; i < 4; i++)
#pragma unroll
        for (int j = 0; j < 4; j++)
#pragma unroll
            for (int r = 0; r < 4; r++) acc[i][j][r] = 0.f;

    stage_load_w(sbase,           A4, B4, m0, n0, 0, tid);
    asm volatile("cp.async.commit_group;" ::: "memory");
    stage_load_w(sbase + WSTAGE,  A4, B4, m0, n0, 1, tid);
    asm volatile("cp.async.commit_group;" ::: "memory");

    uint32_t buf = 0;
    for (int c = 0; c < NCK; c++) {
        asm volatile("cp.async.wait_group 1;" ::: "memory");
        __syncthreads();
        if (c + 2 < NCK) {
            uint32_t nb = buf + 2; if (nb >= NSTAGE) nb -= NSTAGE;
            stage_load_w(sbase + nb * WSTAGE, A4, B4, m0, n0, c + 2, tid);
        }
        asm volatile("cp.async.commit_group;" ::: "memory");

        const uint32_t sb = sbase + buf * WSTAGE;
        const uint32_t sA = sb;
        const uint32_t sB = sb + WTBA;

#pragma unroll
        for (int kk = 0; kk < 4; kk++) {
            uint32_t bb[4][2];
#pragma unroll
            for (int nf2 = 0; nf2 < 2; nf2++) {
                uint32_t off = (uint32_t)(wn + nf2 * 16 + brow) * 128 + kk * 32 + bcolb;
                off ^= (off >> 3) & 0x70;
                LDSM4(bb[nf2*2+0][0], bb[nf2*2+0][1], bb[nf2*2+1][0], bb[nf2*2+1][1], sB + off);
            }
#pragma unroll
            for (int mf = 0; mf < 4; mf++) {
                uint32_t off = (uint32_t)(wm + mf * 16 + arow) * 128 + kk * 32 + acolb;
                off ^= (off >> 3) & 0x70;
                uint32_t a0, a1, a2, a3;
                LDSM4(a0, a1, a2, a3, sA + off);
#pragma unroll
                for (int nf = 0; nf < 4; nf++)
                    MMA16816F16(acc[mf][nf], a0, a1, a2, a3, bb[nf][0], bb[nf][1]);
            }
        }
        buf = buf + 1; if (buf >= NSTAGE) buf = 0;
    }

    const int g  = lane >> 2;
    const int tq = lane & 3;
#pragma unroll
    for (int mf = 0; mf < 4; mf++) {
#pragma unroll
        for (int nf = 0; nf < 4; nf++) {
            int rr = m0 + wm + mf * 16 + g;
            int cc = n0 + wn + nf * 8 + tq * 2;
            *(float2*)&C[(size_t)rr * DMODEL + cc]       = make_float2(acc[mf][nf][0], acc[mf][nf][1]);
            *(float2*)&C[(size_t)(rr + 8) * DMODEL + cc] = make_float2(acc[mf][nf][2], acc[mf][nf][3]);
        }
    }
}

// ---- narrow core: 128x64 CTA tile (qkv). Stage: A 16K + B 8K = 24KB ---------
#define NTBA 16384
#define NTBB 8192
#define NSTG (NTBA + NTBB)          // 24576
#define NGEMM_SMEM (NSTAGE*NSTG)    // 73728

__device__ __forceinline__ void stage_load_n(uint32_t sb,
    const uint4* __restrict__ A4, const uint4* __restrict__ B4,
    int m0, int n0, int c, int tid)
{
    const int q = tid & 7;
    const int r0 = tid >> 3;
#pragma unroll
    for (int it = 0; it < 4; it++) {
        int row = r0 + it * 32;
        uint32_t off = row * 128 + q * 16;
        off ^= (off >> 3) & 0x70;
        cp16(sb + off, A4 + (size_t)(m0 + row) * 128 + c * 8 + q);
    }
#pragma unroll
    for (int it = 0; it < 2; it++) {
        int row = r0 + it * 32;
        uint32_t off = row * 128 + q * 16;
        off ^= (off >> 3) & 0x70;
        cp16(sb + NTBA + off, B4 + (size_t)(n0 + row) * 128 + c * 8 + q);
    }
}

// -------- fused QKV GEMM + RoPE(LUT) + transpose + fp16 stores ----------------
#define QSCALE 0.18033688011112042f

__global__ void __launch_bounds__(256, 2) qkv_gemm(
    const __half* __restrict__ xh_,
    const __half* __restrict__ wq_, const __half* __restrict__ wk_,
    const __half* __restrict__ wv_,
    __half* __restrict__ qhf, __half* __restrict__ khf, __half* __restrict__ vhf,
    float* __restrict__ kc, float* __restrict__ vc,
    const float2* __restrict__ rope)
{
    extern __shared__ char smem[];
    const uint32_t sbase = smem_to_u32(smem);
    const int tid = threadIdx.x;
    const int wid = tid >> 5;
    const int lane = tid & 31;
    const int m0 = blockIdx.y * 128;
    const int n0 = blockIdx.x * 64;
    const int which = blockIdx.z;
    const int wm = (wid & 3) * 32;
    const int wn = (wid >> 2) * 32;
    const int t  = lane >> 3;
    const int li = lane & 7;
    const int arow  = (t & 1) * 8 + li;
    const int acolb = (t >> 1) * 16;
    const int brow  = ((t >> 1) & 1) * 8 + li;
    const int bcolb = (t & 1) * 16;

    const __half* B_ = (which == 0) ? wq_ : (which == 1) ? wk_ : wv_;
    const uint4* A4 = (const uint4*)xh_;
    const uint4* B4 = (const uint4*)B_;

    float acc[2][4][4];
#pragma unroll
    for (int i = 0; i < 2; i++)
#pragma unroll
        for (int j = 0; j < 4; j++)
#pragma unroll
            for (int r = 0; r < 4; r++) acc[i][j][r] = 0.f;

    stage_load_n(sbase,         A4, B4, m0, n0, 0, tid);
    asm volatile("cp.async.commit_group;" ::: "memory");
    stage_load_n(sbase + NSTG,  A4, B4, m0, n0, 1, tid);
    asm volatile("cp.async.commit_group;" ::: "memory");

    uint32_t buf = 0;
    for (int c = 0; c < NCK; c++) {
        asm volatile("cp.async.wait_group 1;" ::: "memory");
        __syncthreads();
        if (c + 2 < NCK) {
            uint32_t nb = buf + 2; if (nb >= NSTAGE) nb -= NSTAGE;
            stage_load_n(sbase + nb * NSTG, A4, B4, m0, n0, c + 2, tid);
        }
        asm volatile("cp.async.commit_group;" ::: "memory");

        const uint32_t sb = sbase + buf * NSTG;
        const uint32_t sA = sb;
        const uint32_t sB = sb + NTBA;

#pragma unroll
        for (int kk = 0; kk < 4; kk++) {
            uint32_t bb[4][2];
#pragma unroll
            for (int nf2 = 0; nf2 < 2; nf2++) {
                uint32_t off = (uint32_t)(wn + nf2 * 16 + brow) * 128 + kk * 32 + bcolb;
                off ^= (off >> 3) & 0x70;
                LDSM4(bb[nf2*2+0][0], bb[nf2*2+0][1], bb[nf2*2+1][0], bb[nf2*2+1][1], sB + off);
            }
#pragma unroll
            for (int mf = 0; mf < 2; mf++) {
                uint32_t off = (uint32_t)(wm + mf * 16 + arow) * 128 + kk * 32 + acolb;
                off ^= (off >> 3) & 0x70;
                uint32_t a0, a1, a2, a3;
                LDSM4(a0, a1, a2, a3, sA + off);
#pragma unroll
                for (int nf = 0; nf < 4; nf++)
                    MMA16816F16(acc[mf][nf], a0, a1, a2, a3, bb[nf][0], bb[nf][1]);
            }
        }
        buf = buf + 1; if (buf >= NSTAGE) buf = 0;
    }

    const int g  = lane >> 2;
    const int tq = lane & 3;
#pragma unroll
    for (int mf = 0; mf < 2; mf++) {
#pragma unroll
        for (int nf = 0; nf < 4; nf++) {
            int cc = n0 + wn + nf * 8 + tq * 2;
            int hh = cc >> 6;
            int d  = cc & 63;
            int p  = d >> 1;
#pragma unroll
            for (int r = 0; r < 2; r++) {
                int rr = m0 + wm + mf * 16 + g + r * 8;
                float a = acc[mf][nf][r*2], bv = acc[mf][nf][r*2+1];
                int s  = rr & (SEQ - 1);
                int bb = rr >> 11;
                size_t dst = ((size_t)(bb * NHEADS + hh) * SEQ + s) * HDIM + d;
                if (which == 2) {
                    *(float2*)(vc + dst) = make_float2(a, bv);
                    *(__half2*)(vhf + dst) = __floats2half2_rn(a, bv);
                } else {
                    float2 cs = rope[(s << 5) + p];
                    float na = a * cs.x - bv * cs.y;
                    float nb = a * cs.y + bv * cs.x;
                    if (which == 0) {
                        *(__half2*)(qhf + dst) = __floats2half2_rn(na * QSCALE, nb * QSCALE);
                    } else {
                        *(float2*)(kc + dst) = make_float2(na, nb);
                        *(__half2*)(khf + dst) = __floats2half2_rn(na, nb);
                    }
                }
            }
        }
    }
}

// ---------------- tensor-core causal flash attention (fp16, Bc=128) ----------
#define FQ 0
#define FST 16384
#define FSTAGE 32768
#define FLASH_SMEM (FST + 2*FSTAGE)   // 81920

__device__ __forceinline__ void flash_stage(uint32_t st,
    const uint4* __restrict__ K4, const uint4* __restrict__ V4,
    int k0, int tid)
{
#pragma unroll
    for (int it = 0; it < 4; it++) {
        int idx = tid + it * 256;
        int row = idx >> 3, q = idx & 7;
        uint32_t off = row * 128 + q * 16;
        off ^= (off >> 3) & 0x70;
        size_t g = (size_t)(k0 + row) * 8 + q;
        cp16(st + off,           K4 + g);
        cp16(st + 16384 + off,   V4 + g);
    }
}

__global__ void __launch_bounds__(256, 1) flash_mma(
    const __half* __restrict__ qhf_, const __half* __restrict__ khf_,
    const __half* __restrict__ vhf_,
    __half* __restrict__ O)
{
    extern __shared__ char smem[];
    const uint32_t sb = smem_to_u32(smem);
    const int tid = threadIdx.x;
    const int wid = tid >> 5;
    const int lane = tid & 31;
    const int qt = gridDim.x - 1 - blockIdx.x;
    const int h  = blockIdx.y;
    const int b  = blockIdx.z;
    const int q0 = qt * 128;
    const size_t head = (size_t)(b * NHEADS + h) * SEQ;

    const uint4* Q4 = (const uint4*)qhf_ + (head + q0) * 8;
    const uint4* K4 = (const uint4*)khf_ + head * 8;
    const uint4* V4 = (const uint4*)vhf_ + head * 8;

    const int t  = lane >> 3;
    const int li = lane & 7;
    const int arow  = (t & 1) * 8 + li;
    const int acolb = (t >> 1) * 16;
    const int brow  = ((t >> 1) & 1) * 8 + li;
    const int bcolb = (t & 1) * 16;
    const int vrow  = (t & 1) * 8 + li;
    const int vcsel = (t >> 1);

#pragma unroll
    for (int it = 0; it < 4; it++) {
        int idx = tid + it * 256;
        int row = idx >> 3, q = idx & 7;
        uint32_t off = row * 128 + q * 16;
        off ^= (off >> 3) & 0x70;
        cp16(sb + FQ + off, Q4 + (size_t)row * 8 + q);
    }
    flash_stage(sb + FST, K4, V4, 0, tid);
    asm volatile("cp.async.commit_group;" ::: "memory");

    const int nkt = qt + 1;

    uint32_t qA[4][4];
    float out[8][4];
#pragma unroll
    for (int nf = 0; nf < 8; nf++)
#pragma unroll
        for (int r = 0; r < 4; r++) out[nf][r] = 0.f;

    float m0 = -1e30f, m1 = -1e30f, l0 = 0.f, l1 = 0.f;
    const int r0g = q0 + wid * 16 + (lane >> 2);
    const int r1g = r0g + 8;

    for (int kt = 0; kt < nkt; kt++) {
        __syncthreads();
        if (kt + 1 < nkt) {
            flash_stage(sb + FST + (uint32_t)((kt + 1) & 1) * FSTAGE,
                        K4, V4, (kt + 1) * 128, tid);
            asm volatile("cp.async.commit_group;" ::: "memory");
            asm volatile("cp.async.wait_group 1;" ::: "memory");
        } else {
            asm volatile("cp.async.wait_group 0;" ::: "memory");
        }
        __syncthreads();

        if (kt == 0) {
#pragma unroll
            for (int kk = 0; kk < 4; kk++) {
                uint32_t off = (uint32_t)(wid * 16 + arow) * 128 + kk * 32 + acolb;
                off ^= (off >> 3) & 0x70;
                LDSM4(qA[kk][0], qA[kk][1], qA[kk][2], qA[kk][3], sb + FQ + off);
            }
        }

        const uint32_t st = sb + FST + (uint32_t)(kt & 1) * FSTAGE;
        const uint32_t sK = st, sV = st + 16384;

        float sacc[16][4];
#pragma unroll
        for (int nf = 0; nf < 16; nf++)
#pragma unroll
            for (int r = 0; r < 4; r++) sacc[nf][r] = 0.f;

#pragma unroll
        for (int kk = 0; kk < 4; kk++) {
#pragma unroll
            for (int nfp = 0; nfp < 8; nfp++) {
                uint32_t off = (uint32_t)(nfp * 16 + brow) * 128 + kk * 32 + bcolb;
                off ^= (off >> 3) & 0x70;
                uint32_t b0, b1, b2, b3;
                LDSM4(b0, b1, b2, b3, sK + off);
                MMA16816F16(sacc[nfp*2],   qA[kk][0], qA[kk][1], qA[kk][2], qA[kk][3], b0, b1);
                MMA16816F16(sacc[nfp*2+1], qA[kk][0], qA[kk][1], qA[kk][2], qA[kk][3], b2, b3);
            }
        }

        const bool domask = (kt == nkt - 1);
        float mx0 = -1e30f, mx1 = -1e30f;
#pragma unroll
        for (int nf = 0; nf < 16; nf++) {
            int key = kt * 128 + nf * 8 + (lane & 3) * 2;
            float s0 = sacc[nf][0];
            float s1 = sacc[nf][1];
            float s2 = sacc[nf][2];
            float s3 = sacc[nf][3];
            if (domask) {
                if (key     > r0g) s0 = -1e30f;
                if (key + 1 > r0g) s1 = -1e30f;
                if (key     > r1g) s2 = -1e30f;
                if (key + 1 > r1g) s3 = -1e30f;
            }
            sacc[nf][0] = s0; sacc[nf][1] = s1; sacc[nf][2] = s2; sacc[nf][3] = s3;
            mx0 = fmaxf(mx0, fmaxf(s0, s1));
            mx1 = fmaxf(mx1, fmaxf(s2, s3));
        }
        mx0 = fmaxf(mx0, __shfl_xor_sync(0xffffffffu, mx0, 1));
        mx0 = fmaxf(mx0, __shfl_xor_sync(0xffffffffu, mx0, 2));
        mx1 = fmaxf(mx1, __shfl_xor_sync(0xffffffffu, mx1, 1));
        mx1 = fmaxf(mx1, __shfl_xor_sync(0xffffffffu, mx1, 2));

        float mn0 = fmaxf(m0, mx0), mn1 = fmaxf(m1, mx1);
        float al0 = ex2f(m0 - mn0), al1 = ex2f(m1 - mn1);

#pragma unroll
        for (int nf = 0; nf < 8; nf++) {
            out[nf][0] *= al0; out[nf][1] *= al0;
            out[nf][2] *= al1; out[nf][3] *= al1;
        }

        float sum0 = 0.f, sum1 = 0.f;
#pragma unroll
        for (int kk = 0; kk < 8; kk++) {
            uint32_t ph[4];
#pragma unroll
            for (int half = 0; half < 2; half++) {
                int nf = kk * 2 + half;
                float p0 = ex2f(sacc[nf][0] - mn0);
                float p1 = ex2f(sacc[nf][1] - mn0);
                float p2 = ex2f(sacc[nf][2] - mn1);
                float p3 = ex2f(sacc[nf][3] - mn1);
                sum0 += p0 + p1;
                sum1 += p2 + p3;
                __half2 a01 = __floats2half2_rn(p0, p1);
                __half2 a23 = __floats2half2_rn(p2, p3);
                ph[half*2]     = *(uint32_t*)&a01;
                ph[half*2 + 1] = *(uint32_t*)&a23;
            }
#pragma unroll
            for (int jp = 0; jp < 8; jp += 2) {
                uint32_t off = (uint32_t)(kk * 16 + vrow) * 128 + (jp + vcsel) * 16;
                off ^= (off >> 3) & 0x70;
                uint32_t v0, v1, v2, v3;
                LDSM4T(v0, v1, v2, v3, sV + off);
                MMA16816F16(out[jp],   ph[0], ph[1], ph[2], ph[3], v0, v1);
                MMA16816F16(out[jp+1], ph[0], ph[1], ph[2], ph[3], v2, v3);
            }
        }
        sum0 += __shfl_xor_sync(0xffffffffu, sum0, 1);
        sum0 += __shfl_xor_sync(0xffffffffu, sum0, 2);
        sum1 += __shfl_xor_sync(0xffffffffu, sum1, 1);
        sum1 += __shfl_xor_sync(0xffffffffu, sum1, 2);
        l0 = l0 * al0 + sum0;
        l1 = l1 * al1 + sum1;
        m0 = mn0; m1 = mn1;
    }

    float inv0 = 1.f / l0, inv1 = 1.f / l1;
#pragma unroll
    for (int nf = 0; nf < 8; nf++) {
        int col = h * HDIM + nf * 8 + (lane & 3) * 2;
        size_t i0 = (size_t)(b * SEQ + r0g) * DMODEL + col;
        size_t i1 = (size_t)(b * SEQ + r1g) * DMODEL + col;
        *(__half2*)(O + i0) = __floats2half2_rn(out[nf][0] * inv0, out[nf][1] * inv0);
        *(__half2*)(O + i1) = __floats2half2_rn(out[nf][2] * inv1, out[nf][3] * inv1);
    }
}

// ---------------- launcher ---------------------------------------------------
extern "C" void kernel_launch(void* const* d_in, const int* in_sizes, int n_in,
                              void* d_out, int out_size)
{
    const float* x  = (const float*)d_in[0];
    const float* Wq = (const float*)d_in[2];
    const float* Wk = (const float*)d_in[3];
    const float* Wv = (const float*)d_in[4];
    const float* Wo = (const float*)d_in[5];
    float* out = (float*)d_out;

    float *kfb, *vfb;
    cudaGetSymbolAddress((void**)&kfb, g_kfb);
    cudaGetSymbolAddress((void**)&vfb, g_vfb);

    __half *xh, *wq, *wk, *wv, *wo, *qhf, *khf, *vhf;
    float2* rope;
    cudaGetSymbolAddress((void**)&xh, g_xh);
    cudaGetSymbolAddress((void**)&wq, g_wq);
    cudaGetSymbolAddress((void**)&wk, g_wk);
    cudaGetSymbolAddress((void**)&wv, g_wv);
    cudaGetSymbolAddress((void**)&wo, g_wo);
    cudaGetSymbolAddress((void**)&qhf, g_qhf);
    cudaGetSymbolAddress((void**)&khf, g_khf);
    cudaGetSymbolAddress((void**)&vhf, g_vhf);
    cudaGetSymbolAddress((void**)&rope, g_rope);

    float* kdst;
    float* vdst;
    if (out_size >= OUTN + 2 * KVN) {
        kdst = out + OUTN;
        vdst = out + OUTN + KVN;
    } else {
        kdst = kfb;
        vdst = vfb;
    }

    cudaFuncSetAttribute(mma_gemm, cudaFuncAttributeMaxDynamicSharedMemorySize, WGEMM_SMEM);
    cudaFuncSetAttribute(qkv_gemm, cudaFuncAttributeMaxDynamicSharedMemorySize, NGEMM_SMEM);
    cudaFuncSetAttribute(flash_mma, cudaFuncAttributeMaxDynamicSharedMemorySize, FLASH_SMEM);

    RopeTab tab;
    for (int p = 0; p < 32; p++) {
        double invf = exp(-(double)p * (log(10000.0) / 32.0));
        float hi = (float)invf;
        tab.hi[p] = hi;
        tab.lo[p] = (float)(invf - (double)hi);
    }

    // merged conversions + rope LUT
    ConvPtrs cp;
    cp.x  = (const float4*)x;
    cp.xh = (__half2*)xh;
    cp.w[0] = (const float4*)Wq; cp.wd[0] = (__half2*)wq;
    cp.w[1] = (const float4*)Wk; cp.wd[1] = (__half2*)wk;
    cp.w[2] = (const float4*)Wv; cp.wd[2] = (__half2*)wv;
    cp.w[3] = (const float4*)Wo; cp.wd[3] = (__half2*)wo;
    cp.rope = rope;
    dim3 cgrid(OUTN/4/256, 6);
    conv_all<<<cgrid, 256>>>(cp, tab, OUTN/4, WN/4);

    // fused QKV projection + RoPE(LUT) (128x64 tiles — R13 config + LUT)
    dim3 ggrid(DMODEL / 64, MROWS / 128, 3);   // (16, 32, 3) = 1536 CTAs
    qkv_gemm<<<ggrid, 256, NGEMM_SMEM>>>(xh, wq, wk, wv,
                                         qhf, khf, vhf,
                                         kdst, vdst, rope);

    // tensor-core flash attention (fp16, Bc=128, natural regs)
    dim3 fgrid(SEQ / 128, NHEADS, BATCH);      // (16, 16, 2)
    flash_mma<<<fgrid, 256, FLASH_SMEM>>>(qhf, khf, vhf, xh);

    // output projection (128x128 tiles — R14 config)
    dim3 ogrid(DMODEL / 128, MROWS / 128);     // (8, 32) = 256 CTAs
    mma_gemm<<<ogrid, 256, WGEMM_SMEM>>>(xh, wo, out);
}

// round 16
// speedup vs baseline: 1.0806x; 1.0806x over previous
#include <cuda_runtime.h>
#include <cuda_bf16.h>
#include <cuda_fp16.h>
#include <math.h>
#include <stdint.h>

// Problem constants
#define BATCH 2
#define SEQ 2048
#define DMODEL 1024
#define NHEADS 16
#define HDIM 64
#define MROWS (BATCH*SEQ)              // 4096
#define OUTN  (BATCH*SEQ*DMODEL)       // 4194304
#define KVN   (BATCH*NHEADS*SEQ*HDIM)  // 4194304
#define WN    (DMODEL*DMODEL)          // 1048576

// ---------------- scratch (device globals; no allocations allowed) ----------
__device__ float g_kfb[KVN];
__device__ float g_vfb[KVN];
__device__ __half g_xh[OUTN];          // activation fp16 (x, then attn-out)
__device__ __half g_wq[WN], g_wk[WN], g_wv[WN], g_wo[WN];   // weights fp16
__device__ __half g_qhf[KVN];          // Q fp16 (pre-scaled by 0.125*log2e)
__device__ __half g_khf[KVN];          // K fp16
__device__ __half g_vhf[KVN];          // V fp16

// ====================== helpers ==============================================
__device__ __forceinline__ uint32_t smem_to_u32(const void* p) {
    uint32_t a;
    asm("{ .reg .u64 t; cvta.to.shared.u64 t, %1; cvt.u32.u64 %0, t; }"
        : "=r"(a) : "l"(p));
    return a;
}

__device__ __forceinline__ void cp16(uint32_t saddr, const void* g) {
    asm volatile("cp.async.cg.shared.global [%0], [%1], 16;"
                 :: "r"(saddr), "l"(g) : "memory");
}

__device__ __forceinline__ float ex2f(float x) {
    float y;
    asm("ex2.approx.ftz.f32 %0, %1;" : "=f"(y) : "f"(x));
    return y;
}

#define LDSM4(r0, r1, r2, r3, addr) \
    asm volatile("ldmatrix.sync.aligned.m8n8.x4.shared.b16 {%0,%1,%2,%3}, [%4];" \
                 : "=r"(r0), "=r"(r1), "=r"(r2), "=r"(r3) : "r"(addr))

#define LDSM4T(r0, r1, r2, r3, addr) \
    asm volatile("ldmatrix.sync.aligned.m8n8.x4.trans.shared.b16 {%0,%1,%2,%3}, [%4];" \
                 : "=r"(r0), "=r"(r1), "=r"(r2), "=r"(r3) : "r"(addr))

#define MMA16816F16(d, a0, a1, a2, a3, b0, b1) \
    asm volatile("mma.sync.aligned.m16n8k16.row.col.f32.f16.f16.f32 " \
                 "{%0,%1,%2,%3}, {%4,%5,%6,%7}, {%8,%9}, {%0,%1,%2,%3};" \
                 : "+f"((d)[0]), "+f"((d)[1]), "+f"((d)[2]), "+f"((d)[3]) \
                 : "r"(a0), "r"(a1), "r"(a2), "r"(a3), "r"(b0), "r"(b1))

struct RopeTab { float hi[32]; float lo[32]; };

// ====================== merged conversions ====================================
// slice 0: x -> fp16; slices 1-4: weights -> fp16
struct ConvPtrs {
    const float4* x;
    __half2* xh;
    const float4* w[4];
    __half2* wd[4];
};

__global__ void conv_all(ConvPtrs p, int nx4, int nw4)
{
    int i = blockIdx.x * blockDim.x + threadIdx.x;
    int sl = blockIdx.y;
    if (sl == 0) {
        if (i >= nx4) return;
        float4 v = p.x[i];
        p.xh[2*i]   = __floats2half2_rn(v.x, v.y);
        p.xh[2*i+1] = __floats2half2_rn(v.z, v.w);
    } else {
        if (i >= nw4) return;
        int w = sl - 1;
        float4 v = p.w[w][i];
        p.wd[w][2*i]   = __floats2half2_rn(v.x, v.y);
        p.wd[w][2*i+1] = __floats2half2_rn(v.z, v.w);
    }
}

// ====================== GEMM cores (3-stage ring, 1 sync/chunk) ===============
#define NCK 16
#define NSTAGE 3

// ---- wide core: 128x128 CTA tile (ogemm). Stage: A 16K + B 16K = 32KB -------
#define WTBA 16384
#define WSTAGE 32768
#define WGEMM_SMEM (NSTAGE*WSTAGE)   // 98304

__device__ __forceinline__ void stage_load_w(uint32_t sb,
    const uint4* __restrict__ A4, const uint4* __restrict__ B4,
    int m0, int n0, int c, int tid)
{
    const int q = tid & 7;
    const int r0 = tid >> 3;
#pragma unroll
    for (int it = 0; it < 4; it++) {
        int row = r0 + it * 32;
        uint32_t off = row * 128 + q * 16;
        off ^= (off >> 3) & 0x70;
        cp16(sb + off,        A4 + (size_t)(m0 + row) * 128 + c * 8 + q);
        cp16(sb + WTBA + off, B4 + (size_t)(n0 + row) * 128 + c * 8 + q);
    }
}

__global__ void __launch_bounds__(256, 2) mma_gemm(const __half* __restrict__ A_,
                                                   const __half* __restrict__ B_,
                                                   float* __restrict__ C)
{
    extern __shared__ char smem[];
    const uint32_t sbase = smem_to_u32(smem);
    const int tid = threadIdx.x;
    const int wid = tid >> 5;
    const int lane = tid & 31;
    const int m0 = blockIdx.y * 128;
    const int n0 = blockIdx.x * 128;
    const int wm = (wid & 1) * 64;
    const int wn = (wid >> 1) * 32;
    const int t  = lane >> 3;
    const int li = lane & 7;
    const int arow  = (t & 1) * 8 + li;
    const int acolb = (t >> 1) * 16;
    const int brow  = ((t >> 1) & 1) * 8 + li;
    const int bcolb = (t & 1) * 16;

    const uint4* A4 = (const uint4*)A_;
    const uint4* B4 = (const uint4*)B_;

    float acc[4][4][4];
#pragma unroll
    for (int i = 0; i < 4; i++)
#pragma unroll
        for (int j = 0; j < 4; j++)
#pragma unroll
            for (int r = 0; r < 4; r++) acc[i][j][r] = 0.f;

    stage_load_w(sbase,           A4, B4, m0, n0, 0, tid);
    asm volatile("cp.async.commit_group;" ::: "memory");
    stage_load_w(sbase + WSTAGE,  A4, B4, m0, n0, 1, tid);
    asm volatile("cp.async.commit_group;" ::: "memory");

    uint32_t buf = 0;
    for (int c = 0; c < NCK; c++) {
        asm volatile("cp.async.wait_group 1;" ::: "memory");
        __syncthreads();
        if (c + 2 < NCK) {
            uint32_t nb = buf + 2; if (nb >= NSTAGE) nb -= NSTAGE;
            stage_load_w(sbase + nb * WSTAGE, A4, B4, m0, n0, c + 2, tid);
        }
        asm volatile("cp.async.commit_group;" ::: "memory");

        const uint32_t sb = sbase + buf * WSTAGE;
        const uint32_t sA = sb;
        const uint32_t sB = sb + WTBA;

#pragma unroll
        for (int kk = 0; kk < 4; kk++) {
            uint32_t bb[4][2];
#pragma unroll
            for (int nf2 = 0; nf2 < 2; nf2++) {
                uint32_t off = (uint32_t)(wn + nf2 * 16 + brow) * 128 + kk * 32 + bcolb;
                off ^= (off >> 3) & 0x70;
                LDSM4(bb[nf2*2+0][0], bb[nf2*2+0][1], bb[nf2*2+1][0], bb[nf2*2+1][1], sB + off);
            }
#pragma unroll
            for (int mf = 0; mf < 4; mf++) {
                uint32_t off = (uint32_t)(wm + mf * 16 + arow) * 128 + kk * 32 + acolb;
                off ^= (off >> 3) & 0x70;
                uint32_t a0, a1, a2, a3;
                LDSM4(a0, a1, a2, a3, sA + off);
#pragma unroll
                for (int nf = 0; nf < 4; nf++)
                    MMA16816F16(acc[mf][nf], a0, a1, a2, a3, bb[nf][0], bb[nf][1]);
            }
        }
        buf = buf + 1; if (buf >= NSTAGE) buf = 0;
    }

    const int g  = lane >> 2;
    const int tq = lane & 3;
#pragma unroll
    for (int mf = 0; mf < 4; mf++) {
#pragma unroll
        for (int nf = 0; nf < 4; nf++) {
            int rr = m0 + wm + mf * 16 + g;
            int cc = n0 + wn + nf * 8 + tq * 2;
            *(float2*)&C[(size_t)rr * DMODEL + cc]       = make_float2(acc[mf][nf][0], acc[mf][nf][1]);
            *(float2*)&C[(size_t)(rr + 8) * DMODEL + cc] = make_float2(acc[mf][nf][2], acc[mf][nf][3]);
        }
    }
}

// ---- narrow core: 128x64 CTA tile (qkv). Stage: A 16K + B 8K = 24KB ---------
#define NTBA 16384
#define NTBB 8192
#define NSTG (NTBA + NTBB)          // 24576
#define NGEMM_SMEM (NSTAGE*NSTG)    // 73728

__device__ __forceinline__ void stage_load_n(uint32_t sb,
    const uint4* __restrict__ A4, const uint4* __restrict__ B4,
    int m0, int n0, int c, int tid)
{
    const int q = tid & 7;
    const int r0 = tid >> 3;
#pragma unroll
    for (int it = 0; it < 4; it++) {
        int row = r0 + it * 32;
        uint32_t off = row * 128 + q * 16;
        off ^= (off >> 3) & 0x70;
        cp16(sb + off, A4 + (size_t)(m0 + row) * 128 + c * 8 + q);
    }
#pragma unroll
    for (int it = 0; it < 2; it++) {
        int row = r0 + it * 32;
        uint32_t off = row * 128 + q * 16;
        off ^= (off >> 3) & 0x70;
        cp16(sb + NTBA + off, B4 + (size_t)(n0 + row) * 128 + c * 8 + q);
    }
}

// -------- fused QKV GEMM + RoPE(sincosf) + transpose + fp16 stores ------------
#define QSCALE 0.18033688011112042f

__global__ void __launch_bounds__(256, 2) qkv_gemm(
    const __half* __restrict__ xh_,
    const __half* __restrict__ wq_, const __half* __restrict__ wk_,
    const __half* __restrict__ wv_,
    __half* __restrict__ qhf, __half* __restrict__ khf, __half* __restrict__ vhf,
    float* __restrict__ kc, float* __restrict__ vc, RopeTab tab)
{
    extern __shared__ char smem[];
    const uint32_t sbase = smem_to_u32(smem);
    const int tid = threadIdx.x;
    const int wid = tid >> 5;
    const int lane = tid & 31;
    const int m0 = blockIdx.y * 128;
    const int n0 = blockIdx.x * 64;
    const int which = blockIdx.z;
    const int wm = (wid & 3) * 32;
    const int wn = (wid >> 2) * 32;
    const int t  = lane >> 3;
    const int li = lane & 7;
    const int arow  = (t & 1) * 8 + li;
    const int acolb = (t >> 1) * 16;
    const int brow  = ((t >> 1) & 1) * 8 + li;
    const int bcolb = (t & 1) * 16;

    const __half* B_ = (which == 0) ? wq_ : (which == 1) ? wk_ : wv_;
    const uint4* A4 = (const uint4*)xh_;
    const uint4* B4 = (const uint4*)B_;

    float acc[2][4][4];
#pragma unroll
    for (int i = 0; i < 2; i++)
#pragma unroll
        for (int j = 0; j < 4; j++)
#pragma unroll
            for (int r = 0; r < 4; r++) acc[i][j][r] = 0.f;

    stage_load_n(sbase,         A4, B4, m0, n0, 0, tid);
    asm volatile("cp.async.commit_group;" ::: "memory");
    stage_load_n(sbase + NSTG,  A4, B4, m0, n0, 1, tid);
    asm volatile("cp.async.commit_group;" ::: "memory");

    uint32_t buf = 0;
    for (int c = 0; c < NCK; c++) {
        asm volatile("cp.async.wait_group 1;" ::: "memory");
        __syncthreads();
        if (c + 2 < NCK) {
            uint32_t nb = buf + 2; if (nb >= NSTAGE) nb -= NSTAGE;
            stage_load_n(sbase + nb * NSTG, A4, B4, m0, n0, c + 2, tid);
        }
        asm volatile("cp.async.commit_group;" ::: "memory");

        const uint32_t sb = sbase + buf * NSTG;
        const uint32_t sA = sb;
        const uint32_t sB = sb + NTBA;

#pragma unroll
        for (int kk = 0; kk < 4; kk++) {
            uint32_t bb[4][2];
#pragma unroll
            for (int nf2 = 0; nf2 < 2; nf2++) {
                uint32_t off = (uint32_t)(wn + nf2 * 16 + brow) * 128 + kk * 32 + bcolb;
                off ^= (off >> 3) & 0x70;
                LDSM4(bb[nf2*2+0][0], bb[nf2*2+0][1], bb[nf2*2+1][0], bb[nf2*2+1][1], sB + off);
            }
#pragma unroll
            for (int mf = 0; mf < 2; mf++) {
                uint32_t off = (uint32_t)(wm + mf * 16 + arow) * 128 + kk * 32 + acolb;
                off ^= (off >> 3) & 0x70;
                uint32_t a0, a1, a2, a3;
                LDSM4(a0, a1, a2, a3, sA + off);
#pragma unroll
                for (int nf = 0; nf < 4; nf++)
                    MMA16816F16(acc[mf][nf], a0, a1, a2, a3, bb[nf][0], bb[nf][1]);
            }
        }
        buf = buf + 1; if (buf >= NSTAGE) buf = 0;
    }

    const int g  = lane >> 2;
    const int tq = lane & 3;
#pragma unroll
    for (int mf = 0; mf < 2; mf++) {
#pragma unroll
        for (int nf = 0; nf < 4; nf++) {
            int cc = n0 + wn + nf * 8 + tq * 2;
            int hh = cc >> 6;
            int d  = cc & 63;
            int p  = d >> 1;
            float fhi = tab.hi[p], flo = tab.lo[p];
#pragma unroll
            for (int r = 0; r < 2; r++) {
                int rr = m0 + wm + mf * 16 + g + r * 8;
                float a = acc[mf][nf][r*2], bv = acc[mf][nf][r*2+1];
                int s  = rr & (SEQ - 1);
                int bb = rr >> 11;
                size_t dst = ((size_t)(bb * NHEADS + hh) * SEQ + s) * HDIM + d;
                if (which == 2) {
                    *(float2*)(vc + dst) = make_float2(a, bv);
                    *(__half2*)(vhf + dst) = __floats2half2_rn(a, bv);
                } else {
                    float fs = (float)s;
                    float ang = fmaf(fs, flo, fs * fhi);
                    float c, sn;
                    sincosf(ang, &sn, &c);
                    float na = a * c - bv * sn;
                    float nb = a * sn + bv * c;
                    if (which == 0) {
                        *(__half2*)(qhf + dst) = __floats2half2_rn(na * QSCALE, nb * QSCALE);
                    } else {
                        *(float2*)(kc + dst) = make_float2(na, nb);
                        *(__half2*)(khf + dst) = __floats2half2_rn(na, nb);
                    }
                }
            }
        }
    }
}

// ---------------- tensor-core causal flash attention (fp16, Bc=128) ----------
#define FQ 0
#define FST 16384
#define FSTAGE 32768
#define FLASH_SMEM (FST + 2*FSTAGE)   // 81920

__device__ __forceinline__ void flash_stage(uint32_t st,
    const uint4* __restrict__ K4, const uint4* __restrict__ V4,
    int k0, int tid)
{
#pragma unroll
    for (int it = 0; it < 4; it++) {
        int idx = tid + it * 256;
        int row = idx >> 3, q = idx & 7;
        uint32_t off = row * 128 + q * 16;
        off ^= (off >> 3) & 0x70;
        size_t g = (size_t)(k0 + row) * 8 + q;
        cp16(st + off,           K4 + g);
        cp16(st + 16384 + off,   V4 + g);
    }
}

__global__ void __launch_bounds__(256, 1) flash_mma(
    const __half* __restrict__ qhf_, const __half* __restrict__ khf_,
    const __half* __restrict__ vhf_,
    __half* __restrict__ O)
{
    extern __shared__ char smem[];
    const uint32_t sb = smem_to_u32(smem);
    const int tid = threadIdx.x;
    const int wid = tid >> 5;
    const int lane = tid & 31;
    const int qt = gridDim.x - 1 - blockIdx.x;
    const int h  = blockIdx.y;
    const int b  = blockIdx.z;
    const int q0 = qt * 128;
    const size_t head = (size_t)(b * NHEADS + h) * SEQ;

    const uint4* Q4 = (const uint4*)qhf_ + (head + q0) * 8;
    const uint4* K4 = (const uint4*)khf_ + head * 8;
    const uint4* V4 = (const uint4*)vhf_ + head * 8;

    const int t  = lane >> 3;
    const int li = lane & 7;
    const int arow  = (t & 1) * 8 + li;
    const int acolb = (t >> 1) * 16;
    const int brow  = ((t >> 1) & 1) * 8 + li;
    const int bcolb = (t & 1) * 16;
    const int vrow  = (t & 1) * 8 + li;
    const int vcsel = (t >> 1);

#pragma unroll
    for (int it = 0; it < 4; it++) {
        int idx = tid + it * 256;
        int row = idx >> 3, q = idx & 7;
        uint32_t off = row * 128 + q * 16;
        off ^= (off >> 3) & 0x70;
        cp16(sb + FQ + off, Q4 + (size_t)row * 8 + q);
    }
    flash_stage(sb + FST, K4, V4, 0, tid);
    asm volatile("cp.async.commit_group;" ::: "memory");

    const int nkt = qt + 1;

    uint32_t qA[4][4];
    float out[8][4];
#pragma unroll
    for (int nf = 0; nf < 8; nf++)
#pragma unroll
        for (int r = 0; r < 4; r++) out[nf][r] = 0.f;

    float m0 = -1e30f, m1 = -1e30f, l0 = 0.f, l1 = 0.f;
    const int r0g = q0 + wid * 16 + (lane >> 2);
    const int r1g = r0g + 8;

    for (int kt = 0; kt < nkt; kt++) {
        __syncthreads();
        if (kt + 1 < nkt) {
            flash_stage(sb + FST + (uint32_t)((kt + 1) & 1) * FSTAGE,
                        K4, V4, (kt + 1) * 128, tid);
            asm volatile("cp.async.commit_group;" ::: "memory");
            asm volatile("cp.async.wait_group 1;" ::: "memory");
        } else {
            asm volatile("cp.async.wait_group 0;" ::: "memory");
        }
        __syncthreads();

        if (kt == 0) {
#pragma unroll
            for (int kk = 0; kk < 4; kk++) {
                uint32_t off = (uint32_t)(wid * 16 + arow) * 128 + kk * 32 + acolb;
                off ^= (off >> 3) & 0x70;
                LDSM4(qA[kk][0], qA[kk][1], qA[kk][2], qA[kk][3], sb + FQ + off);
            }
        }

        const uint32_t st = sb + FST + (uint32_t)(kt & 1) * FSTAGE;
        const uint32_t sK = st, sV = st + 16384;

        float sacc[16][4];
#pragma unroll
        for (int nf = 0; nf < 16; nf++)
#pragma unroll
            for (int r = 0; r < 4; r++) sacc[nf][r] = 0.f;

#pragma unroll
        for (int kk = 0; kk < 4; kk++) {
#pragma unroll
            for (int nfp = 0; nfp < 8; nfp++) {
                uint32_t off = (uint32_t)(nfp * 16 + brow) * 128 + kk * 32 + bcolb;
                off ^= (off >> 3) & 0x70;
                uint32_t b0, b1, b2, b3;
                LDSM4(b0, b1, b2, b3, sK + off);
                MMA16816F16(sacc[nfp*2],   qA[kk][0], qA[kk][1], qA[kk][2], qA[kk][3], b0, b1);
                MMA16816F16(sacc[nfp*2+1], qA[kk][0], qA[kk][1], qA[kk][2], qA[kk][3], b2, b3);
            }
        }

        const bool domask = (kt == nkt - 1);
        float mx0 = -1e30f, mx1 = -1e30f;
#pragma unroll
        for (int nf = 0; nf < 16; nf++) {
            int key = kt * 128 + nf * 8 + (lane & 3) * 2;
            float s0 = sacc[nf][0];
            float s1 = sacc[nf][1];
            float s2 = sacc[nf][2];
            float s3 = sacc[nf][3];
            if (domask) {
                if (key     > r0g) s0 = -1e30f;
                if (key + 1 > r0g) s1 = -1e30f;
                if (key     > r1g) s2 = -1e30f;
                if (key + 1 > r1g) s3 = -1e30f;
            }
            sacc[nf][0] = s0; sacc[nf][1] = s1; sacc[nf][2] = s2; sacc[nf][3] = s3;
            mx0 = fmaxf(mx0, fmaxf(s0, s1));
            mx1 = fmaxf(mx1, fmaxf(s2, s3));
        }
        mx0 = fmaxf(mx0, __shfl_xor_sync(0xffffffffu, mx0, 1));
        mx0 = fmaxf(mx0, __shfl_xor_sync(0xffffffffu, mx0, 2));
        mx1 = fmaxf(mx1, __shfl_xor_sync(0xffffffffu, mx1, 1));
        mx1 = fmaxf(mx1, __shfl_xor_sync(0xffffffffu, mx1, 2));

        float mn0 = fmaxf(m0, mx0), mn1 = fmaxf(m1, mx1);
        float al0 = ex2f(m0 - mn0), al1 = ex2f(m1 - mn1);

#pragma unroll
        for (int nf = 0; nf < 8; nf++) {
            out[nf][0] *= al0; out[nf][1] *= al0;
            out[nf][2] *= al1; out[nf][3] *= al1;
        }

        float sum0 = 0.f, sum1 = 0.f;
#pragma unroll
        for (int kk = 0; kk < 8; kk++) {
            uint32_t ph[4];
#pragma unroll
            for (int half = 0; half < 2; half++) {
                int nf = kk * 2 + half;
                float p0 = ex2f(sacc[nf][0] - mn0);
                float p1 = ex2f(sacc[nf][1] - mn0);
                float p2 = ex2f(sacc[nf][2] - mn1);
                float p3 = ex2f(sacc[nf][3] - mn1);
                sum0 += p0 + p1;
                sum1 += p2 + p3;
                __half2 a01 = __floats2half2_rn(p0, p1);
                __half2 a23 = __floats2half2_rn(p2, p3);
                ph[half*2]     = *(uint32_t*)&a01;
                ph[half*2 + 1] = *(uint32_t*)&a23;
            }
#pragma unroll
            for (int jp = 0; jp < 8; jp += 2) {
                uint32_t off = (uint32_t)(kk * 16 + vrow) * 128 + (jp + vcsel) * 16;
                off ^= (off >> 3) & 0x70;
                uint32_t v0, v1, v2, v3;
                LDSM4T(v0, v1, v2, v3, sV + off);
                MMA16816F16(out[jp],   ph[0], ph[1], ph[2], ph[3], v0, v1);
                MMA16816F16(out[jp+1], ph[0], ph[1], ph[2], ph[3], v2, v3);
            }
        }
        sum0 += __shfl_xor_sync(0xffffffffu, sum0, 1);
        sum0 += __shfl_xor_sync(0xffffffffu, sum0, 2);
        sum1 += __shfl_xor_sync(0xffffffffu, sum1, 1);
        sum1 += __shfl_xor_sync(0xffffffffu, sum1, 2);
        l0 = l0 * al0 + sum0;
        l1 = l1 * al1 + sum1;
        m0 = mn0; m1 = mn1;
    }

    float inv0 = 1.f / l0, inv1 = 1.f / l1;
#pragma unroll
    for (int nf = 0; nf < 8; nf++) {
        int col = h * HDIM + nf * 8 + (lane & 3) * 2;
        size_t i0 = (size_t)(b * SEQ + r0g) * DMODEL + col;
        size_t i1 = (size_t)(b * SEQ + r1g) * DMODEL + col;
        *(__half2*)(O + i0) = __floats2half2_rn(out[nf][0] * inv0, out[nf][1] * inv0);
        *(__half2*)(O + i1) = __floats2half2_rn(out[nf][2] * inv1, out[nf][3] * inv1);
    }
}

// ---------------- launcher ---------------------------------------------------
extern "C" void kernel_launch(void* const* d_in, const int* in_sizes, int n_in,
                              void* d_out, int out_size)
{
    const float* x  = (const float*)d_in[0];
    const float* Wq = (const float*)d_in[2];
    const float* Wk = (const float*)d_in[3];
    const float* Wv = (const float*)d_in[4];
    const float* Wo = (const float*)d_in[5];
    float* out = (float*)d_out;

    float *kfb, *vfb;
    cudaGetSymbolAddress((void**)&kfb, g_kfb);
    cudaGetSymbolAddress((void**)&vfb, g_vfb);

    __half *xh, *wq, *wk, *wv, *wo, *qhf, *khf, *vhf;
    cudaGetSymbolAddress((void**)&xh, g_xh);
    cudaGetSymbolAddress((void**)&wq, g_wq);
    cudaGetSymbolAddress((void**)&wk, g_wk);
    cudaGetSymbolAddress((void**)&wv, g_wv);
    cudaGetSymbolAddress((void**)&wo, g_wo);
    cudaGetSymbolAddress((void**)&qhf, g_qhf);
    cudaGetSymbolAddress((void**)&khf, g_khf);
    cudaGetSymbolAddress((void**)&vhf, g_vhf);

    float* kdst;
    float* vdst;
    if (out_size >= OUTN + 2 * KVN) {
        kdst = out + OUTN;
        vdst = out + OUTN + KVN;
    } else {
        kdst = kfb;
        vdst = vfb;
    }

    cudaFuncSetAttribute(mma_gemm, cudaFuncAttributeMaxDynamicSharedMemorySize, WGEMM_SMEM);
    cudaFuncSetAttribute(qkv_gemm, cudaFuncAttributeMaxDynamicSharedMemorySize, NGEMM_SMEM);
    cudaFuncSetAttribute(flash_mma, cudaFuncAttributeMaxDynamicSharedMemorySize, FLASH_SMEM);

    RopeTab tab;
    for (int p = 0; p < 32; p++) {
        double invf = exp(-(double)p * (log(10000.0) / 32.0));
        float hi = (float)invf;
        tab.hi[p] = hi;
        tab.lo[p] = (float)(invf - (double)hi);
    }

    // merged conversions (no LUT slice)
    ConvPtrs cp;
    cp.x  = (const float4*)x;
    cp.xh = (__half2*)xh;
    cp.w[0] = (const float4*)Wq; cp.wd[0] = (__half2*)wq;
    cp.w[1] = (const float4*)Wk; cp.wd[1] = (__half2*)wk;
    cp.w[2] = (const float4*)Wv; cp.wd[2] = (__half2*)wv;
    cp.w[3] = (const float4*)Wo; cp.wd[3] = (__half2*)wo;
    dim3 cgrid(OUTN/4/256, 5);
    conv_all<<<cgrid, 256>>>(cp, OUTN/4, WN/4);

    // fused QKV projection + RoPE(sincosf) — exact R13 config
    dim3 ggrid(DMODEL / 64, MROWS / 128, 3);   // (16, 32, 3) = 1536 CTAs
    qkv_gemm<<<ggrid, 256, NGEMM_SMEM>>>(xh, wq, wk, wv,
                                         qhf, khf, vhf,
                                         kdst, vdst, tab);

    // tensor-core flash attention (fp16, Bc=128, natural regs)
    dim3 fgrid(SEQ / 128, NHEADS, BATCH);      // (16, 16, 2)
    flash_mma<<<fgrid, 256, FLASH_SMEM>>>(qhf, khf, vhf, xh);

    // output projection (128x128 tiles — measured-best wide core)
    dim3 ogrid(DMODEL / 128, MROWS / 128);     // (8, 32) = 256 CTAs
    mma_gemm<<<ogrid, 256, WGEMM_SMEM>>>(xh, wo, out);
}